// round 1
// baseline (speedup 1.0000x reference)
#include <cuda_runtime.h>
#include <math.h>

// Problem constants
#define BB 2
#define SS 1024
#define HH 768
#define NH 12
#define DH 64
#define FF 3072
#define NL 4

// ---------------- scratch buffers (device globals: no allocation allowed) ----------------
__device__ float g_h[BB*SS*HH];
__device__ float g_q[BB*SS*HH];
__device__ float g_k[BB*SS*HH];
__device__ float g_v[BB*SS*HH];
__device__ float g_ctx[BB*SS*HH];
__device__ float g_tmp[BB*SS*HH];
__device__ float g_attn[BB*SS*HH];
__device__ float g_inter[BB*SS*FF];
__device__ float g_probs[(long)BB*NH*SS*SS];

// ---------------- generic tiled SGEMM with fused bias / residual / gelu ----------------
// C[M,N] = A[M,K] @ B[K,N] (+bias[N]) (+resid) ; tiles 64x64x16, 4x4 microtile, 256 threads.
// mode 0: single matrix. mode 1: per-(b,h) attention-ctx batch via blockIdx.z.
__global__ __launch_bounds__(256) void gemm_kernel(
    const float* __restrict__ A, const float* __restrict__ Bm,
    const float* __restrict__ bias, const float* __restrict__ resid,
    float* __restrict__ C,
    int M, int N, int K, int lda, int ldb, int ldc,
    int mode, int gelu)
{
    __shared__ __align__(16) float As[16][68];
    __shared__ __align__(16) float Bs[16][68];

    const int tx = threadIdx.x, ty = threadIdx.y;
    const int tid = ty * 16 + tx;
    const int m0 = blockIdx.y * 64, n0 = blockIdx.x * 64;

    long aOff = 0, bOff = 0, cOff = 0;
    if (mode == 1) {
        int z = blockIdx.z;
        aOff = (long)z * M * K;                       // probs contiguous per (b,h)
        int bb = z / NH, hh = z % NH;
        bOff = (long)bb * SS * HH + hh * DH;          // v / ctx slice
        cOff = bOff;
    }

    const int lrow = tid >> 2;   // 0..63  A-tile row
    const int lkq  = tid & 3;    // 0..3   A-tile k quarter
    const int brow = tid >> 4;   // 0..15  B-tile k row
    const int bcol = tid & 15;   // 0..15  B-tile col quarter

    float acc[4][4] = {};

    for (int k0 = 0; k0 < K; k0 += 16) {
        float4 av = *(const float4*)(A + aOff + (long)(m0 + lrow) * lda + k0 + lkq * 4);
        As[lkq*4+0][lrow] = av.x;
        As[lkq*4+1][lrow] = av.y;
        As[lkq*4+2][lrow] = av.z;
        As[lkq*4+3][lrow] = av.w;
        float4 bv = *(const float4*)(Bm + bOff + (long)(k0 + brow) * ldb + n0 + bcol * 4);
        *(float4*)&Bs[brow][bcol*4] = bv;
        __syncthreads();

        #pragma unroll
        for (int kk = 0; kk < 16; kk++) {
            float4 a = *(const float4*)&As[kk][ty*4];
            float4 b = *(const float4*)&Bs[kk][tx*4];
            acc[0][0] += a.x*b.x; acc[0][1] += a.x*b.y; acc[0][2] += a.x*b.z; acc[0][3] += a.x*b.w;
            acc[1][0] += a.y*b.x; acc[1][1] += a.y*b.y; acc[1][2] += a.y*b.z; acc[1][3] += a.y*b.w;
            acc[2][0] += a.z*b.x; acc[2][1] += a.z*b.y; acc[2][2] += a.z*b.z; acc[2][3] += a.z*b.w;
            acc[3][0] += a.w*b.x; acc[3][1] += a.w*b.y; acc[3][2] += a.w*b.z; acc[3][3] += a.w*b.w;
        }
        __syncthreads();
    }

    const int col = n0 + tx * 4;
    float4 bs = bias ? *(const float4*)(bias + col) : make_float4(0.f,0.f,0.f,0.f);
    #pragma unroll
    for (int i = 0; i < 4; i++) {
        int row = m0 + ty * 4 + i;
        float4 rs = resid ? *(const float4*)(resid + (long)row * ldc + col)
                          : make_float4(0.f,0.f,0.f,0.f);
        float4 o;
        o.x = acc[i][0] + bs.x + rs.x;
        o.y = acc[i][1] + bs.y + rs.y;
        o.z = acc[i][2] + bs.z + rs.z;
        o.w = acc[i][3] + bs.w + rs.w;
        if (gelu) {
            o.x = 0.5f * o.x * (1.0f + erff(o.x * 0.70710678118654752f));
            o.y = 0.5f * o.y * (1.0f + erff(o.y * 0.70710678118654752f));
            o.z = 0.5f * o.z * (1.0f + erff(o.z * 0.70710678118654752f));
            o.w = 0.5f * o.w * (1.0f + erff(o.w * 0.70710678118654752f));
        }
        *(float4*)(C + cOff + (long)row * ldc + col) = o;
    }
}

// ---------------- fused attention scores + mask + softmax -> probs ----------------
// Block: (q-tile of 32 rows) x (b,h). 256 threads. Dynamic smem:
//   qs[64][36] transposed q tile, ks[64][66] transposed k tile, sc[32][1024] scores.
__global__ __launch_bounds__(256) void attn_scores_softmax(
    const float* __restrict__ q, const float* __restrict__ k,
    const int* __restrict__ mask, float* __restrict__ probs)
{
    extern __shared__ __align__(16) float sm[];
    float* qs = sm;                      // 64*36
    float* ks = sm + 64*36;              // 64*66
    float* sc = sm + 64*36 + 64*66;      // 32*1024

    const int tid = threadIdx.x;
    const int qt = blockIdx.x;           // 0..31
    const int bh = blockIdx.y;           // 0..23
    const int b = bh / NH, h = bh % NH;
    const int q0 = qt * 32;

    const float* qbase = q + (long)b * SS * HH + h * DH;
    const float* kbase = k + (long)b * SS * HH + h * DH;

    // load q tile (32 rows x 64 dims), transposed to qs[d][row]
    {
        int r = tid >> 4, dq = tid & 15;
        #pragma unroll
        for (int it = 0; it < 2; it++) {
            int row = r + it * 16;
            float4 v = *(const float4*)(qbase + (long)(q0 + row) * HH + dq * 4);
            qs[(dq*4+0)*36 + row] = v.x;
            qs[(dq*4+1)*36 + row] = v.y;
            qs[(dq*4+2)*36 + row] = v.z;
            qs[(dq*4+3)*36 + row] = v.w;
        }
    }

    const int qg = tid >> 5;   // 0..7  -> q rows 4*qg..4*qg+3
    const int kg = tid & 31;   // 0..31 -> k cols 2*kg..2*kg+1

    for (int kt = 0; kt < 16; kt++) {
        const int k0 = kt * 64;
        __syncthreads();  // protect ks reuse (and q-tile on first iter)
        {
            int rk = tid >> 4, dq = tid & 15;
            #pragma unroll
            for (int it = 0; it < 4; it++) {
                int ki = rk + it * 16;
                float4 v = *(const float4*)(kbase + (long)(k0 + ki) * HH + dq * 4);
                ks[(dq*4+0)*66 + ki] = v.x;
                ks[(dq*4+1)*66 + ki] = v.y;
                ks[(dq*4+2)*66 + ki] = v.z;
                ks[(dq*4+3)*66 + ki] = v.w;
            }
        }
        __syncthreads();

        float acc[4][2] = {};
        #pragma unroll 8
        for (int d = 0; d < 64; d++) {
            float4 qv = *(const float4*)&qs[d*36 + qg*4];
            float2 kv = *(const float2*)&ks[d*66 + kg*2];
            acc[0][0] += qv.x * kv.x; acc[0][1] += qv.x * kv.y;
            acc[1][0] += qv.y * kv.x; acc[1][1] += qv.y * kv.y;
            acc[2][0] += qv.z * kv.x; acc[2][1] += qv.z * kv.y;
            acc[3][0] += qv.w * kv.x; acc[3][1] += qv.w * kv.y;
        }
        #pragma unroll
        for (int i = 0; i < 4; i++) {
            float2 st; st.x = acc[i][0]; st.y = acc[i][1];
            *(float2*)&sc[(qg*4+i)*1024 + k0 + kg*2] = st;
        }
    }
    __syncthreads();

    // softmax: 8 warps x 4 rows each
    const int warp = tid >> 5, lane = tid & 31;
    const float scale = 0.125f;  // 1/sqrt(64)
    #pragma unroll
    for (int rr = 0; rr < 4; rr++) {
        int r = warp * 4 + rr;
        float* srow = &sc[r * 1024];
        const int* mrow = mask + (long)b * SS * SS + (long)(q0 + r) * SS;
        float mx = -1e30f;
        for (int c = lane; c < 1024; c += 32) {
            float v = srow[c] * scale + (1.0f - (float)mrow[c]) * (-10000.0f);
            srow[c] = v;
            mx = fmaxf(mx, v);
        }
        #pragma unroll
        for (int o = 16; o; o >>= 1) mx = fmaxf(mx, __shfl_xor_sync(0xffffffffu, mx, o));
        float s = 0.f;
        for (int c = lane; c < 1024; c += 32) {
            float e = __expf(srow[c] - mx);
            srow[c] = e;
            s += e;
        }
        #pragma unroll
        for (int o = 16; o; o >>= 1) s += __shfl_xor_sync(0xffffffffu, s, o);
        float inv = 1.0f / s;
        float* prow = probs + ((long)bh * SS + q0 + r) * SS;
        for (int c = lane; c < 1024; c += 32) prow[c] = srow[c] * inv;
    }
}

// ---------------- LayerNorm (one block per row of 768) ----------------
__global__ __launch_bounds__(256) void ln_kernel(
    const float* __restrict__ x, const float* __restrict__ g,
    const float* __restrict__ b, float* __restrict__ out)
{
    const int row = blockIdx.x;
    const int tid = threadIdx.x;
    const float* xr = x + (long)row * HH;
    float v0 = xr[tid], v1 = xr[tid + 256], v2 = xr[tid + 512];

    __shared__ float red[8];
    float s = v0 + v1 + v2;
    #pragma unroll
    for (int o = 16; o; o >>= 1) s += __shfl_xor_sync(0xffffffffu, s, o);
    if ((tid & 31) == 0) red[tid >> 5] = s;
    __syncthreads();
    float tot = 0.f;
    #pragma unroll
    for (int i = 0; i < 8; i++) tot += red[i];
    float mean = tot * (1.0f / 768.0f);

    float d0 = v0 - mean, d1 = v1 - mean, d2 = v2 - mean;
    float sq = d0*d0 + d1*d1 + d2*d2;
    __syncthreads();
    #pragma unroll
    for (int o = 16; o; o >>= 1) sq += __shfl_xor_sync(0xffffffffu, sq, o);
    if ((tid & 31) == 0) red[tid >> 5] = sq;
    __syncthreads();
    float tot2 = 0.f;
    #pragma unroll
    for (int i = 0; i < 8; i++) tot2 += red[i];
    float rstd = rsqrtf(tot2 * (1.0f / 768.0f) + 1e-12f);

    float* orow = out + (long)row * HH;
    orow[tid]       = d0 * rstd * g[tid]       + b[tid];
    orow[tid + 256] = d1 * rstd * g[tid + 256] + b[tid + 256];
    orow[tid + 512] = d2 * rstd * g[tid + 512] + b[tid + 512];
}

// ---------------- launch ----------------
extern "C" void kernel_launch(void* const* d_in, const int* in_sizes, int n_in,
                              void* d_out, int out_size)
{
    const float* x    = (const float*)d_in[0];
    const int*   mask = (const int*)  d_in[1];
    const float* Wq   = (const float*)d_in[2];
    const float* bq   = (const float*)d_in[3];
    const float* Wk   = (const float*)d_in[4];
    const float* bk   = (const float*)d_in[5];
    const float* Wv   = (const float*)d_in[6];
    const float* bv   = (const float*)d_in[7];
    const float* Wao  = (const float*)d_in[8];
    const float* bao  = (const float*)d_in[9];
    const float* g1   = (const float*)d_in[10];
    const float* b1   = (const float*)d_in[11];
    const float* Wi   = (const float*)d_in[12];
    const float* bi   = (const float*)d_in[13];
    const float* Wfo  = (const float*)d_in[14];
    const float* bfo  = (const float*)d_in[15];
    const float* g2   = (const float*)d_in[16];
    const float* b2   = (const float*)d_in[17];

    float *h_, *q_, *k_, *v_, *ctx_, *tmp_, *attn_, *inter_, *probs_;
    cudaGetSymbolAddress((void**)&h_,     g_h);
    cudaGetSymbolAddress((void**)&q_,     g_q);
    cudaGetSymbolAddress((void**)&k_,     g_k);
    cudaGetSymbolAddress((void**)&v_,     g_v);
    cudaGetSymbolAddress((void**)&ctx_,   g_ctx);
    cudaGetSymbolAddress((void**)&tmp_,   g_tmp);
    cudaGetSymbolAddress((void**)&attn_,  g_attn);
    cudaGetSymbolAddress((void**)&inter_, g_inter);
    cudaGetSymbolAddress((void**)&probs_, g_probs);

    const int smem_scores = (64*36 + 64*66 + 32*1024) * 4;  // 157184 bytes
    cudaFuncSetAttribute(attn_scores_softmax,
                         cudaFuncAttributeMaxDynamicSharedMemorySize, smem_scores);

    const dim3 blk(16, 16);
    const int M = BB * SS;  // 2048

    for (int l = 0; l < NL; l++) {
        const float* hin = (l == 0) ? x : h_;
        const float* wq = Wq + (long)l*HH*HH;
        const float* wk = Wk + (long)l*HH*HH;
        const float* wv = Wv + (long)l*HH*HH;
        const float* wo = Wao + (long)l*HH*HH;
        const float* wi = Wi + (long)l*HH*FF;
        const float* wf = Wfo + (long)l*FF*HH;

        // Q, K, V projections
        gemm_kernel<<<dim3(HH/64, M/64, 1), blk>>>(hin, wq, bq + l*HH, nullptr, q_,
                                                   M, HH, HH, HH, HH, HH, 0, 0);
        gemm_kernel<<<dim3(HH/64, M/64, 1), blk>>>(hin, wk, bk + l*HH, nullptr, k_,
                                                   M, HH, HH, HH, HH, HH, 0, 0);
        gemm_kernel<<<dim3(HH/64, M/64, 1), blk>>>(hin, wv, bv + l*HH, nullptr, v_,
                                                   M, HH, HH, HH, HH, HH, 0, 0);

        // scores + mask + softmax
        attn_scores_softmax<<<dim3(SS/32, BB*NH), 256, smem_scores>>>(q_, k_, mask, probs_);

        // ctx = probs @ v (batched per (b,h))
        gemm_kernel<<<dim3(1, SS/64, BB*NH), blk>>>(probs_, v_, nullptr, nullptr, ctx_,
                                                    SS, DH, SS, SS, HH, HH, 1, 0);

        // attention output proj + residual
        gemm_kernel<<<dim3(HH/64, M/64, 1), blk>>>(ctx_, wo, bao + l*HH, hin, tmp_,
                                                   M, HH, HH, HH, HH, HH, 0, 0);
        ln_kernel<<<M, 256>>>(tmp_, g1 + l*HH, b1 + l*HH, attn_);

        // FFN
        gemm_kernel<<<dim3(FF/64, M/64, 1), blk>>>(attn_, wi, bi + l*FF, nullptr, inter_,
                                                   M, FF, HH, HH, FF, FF, 0, 1);
        gemm_kernel<<<dim3(HH/64, M/64, 1), blk>>>(inter_, wf, bfo + l*HH, attn_, tmp_,
                                                   M, HH, FF, FF, HH, HH, 0, 0);

        float* lnout = (l == NL - 1) ? (float*)d_out : h_;
        ln_kernel<<<M, 256>>>(tmp_, g2 + l*HH, b2 + l*HH, lnout);
    }
}